// round 10
// baseline (speedup 1.0000x reference)
#include <cuda_runtime.h>
#include <cuda_bf16.h>
#include <stdint.h>

#define B     4
#define LQ    128
#define LK    1024
#define D     512
#define DV    512
#define UNITS 256

typedef unsigned long long ull;

// Scratch (device globals — no allocation allowed)
__device__ float g_qp[B * LQ * UNITS];         // [b*LQ+q][u]
__device__ float g_kp[B * LK * UNITS];         // [b*LK+k][u]
__device__ float g_sc[B * LQ * LK];            // raw scores (unmasked region)
__device__ int   g_vlen[B];

__device__ __forceinline__ float tanh_fast(float x) {
    float y;
    asm("tanh.approx.f32 %0, %1;" : "=f"(y) : "f"(x));
    return y;
}
__device__ __forceinline__ ull ffma2(ull a, ull b, ull c) {
    ull d;
    asm("fma.rn.f32x2 %0, %1, %2, %3;" : "=l"(d) : "l"(a), "l"(b), "l"(c));
    return d;
}
__device__ __forceinline__ ull dup2(float x) {
    ull r;
    asm("mov.b64 %0, {%1, %1};" : "=l"(r) : "f"(x));
    return r;
}
__device__ __forceinline__ float2 unpack2(ull v) {
    float2 f;
    asm("mov.b64 {%0, %1}, %2;" : "=f"(f.x), "=f"(f.y) : "l"(v));
    return f;
}
__device__ __forceinline__ uint32_t to_tf32(float x) {
    uint32_t r;
    asm("cvt.rna.tf32.f32 %0, %1;" : "=r"(r) : "f"(x));
    return r;
}
__device__ __forceinline__ void mma_tf32(
    float& d0, float& d1, float& d2, float& d3,
    uint32_t a0, uint32_t a1, uint32_t a2, uint32_t a3,
    uint32_t b0, uint32_t b1)
{
    asm("mma.sync.aligned.m16n8k8.row.col.f32.tf32.tf32.f32 "
        "{%0,%1,%2,%3}, {%4,%5,%6,%7}, {%8,%9}, {%0,%1,%2,%3};"
        : "+f"(d0), "+f"(d1), "+f"(d2), "+f"(d3)
        : "r"(a0), "r"(a1), "r"(a2), "r"(a3), "r"(b0), "r"(b1));
}

// ---------------------------------------------------------------------------
// 1) Projection GEMM via tf32 mma.sync, fragment-native smem, BM=32.
//    rows [0,512): g_qp ; rows [512,4608): g_kp (masked k-tiles exit).
//    CTA 32m x 64n, BK=32, 256 thr = 8 warps, warp tile 32m x 8n.
//    Grid 144 x 4 = 576 CTAs -> balanced waves after vlen exits.
// ---------------------------------------------------------------------------
__global__ __launch_bounds__(256) void proj_kernel(
    const float* __restrict__ query, const float* __restrict__ key,
    const float* __restrict__ Wq,    const float* __restrict__ Wk,
    const void*  __restrict__ vl)
{
    const long long* l = (const long long*)vl;
    const int*       w = (const int*)vl;
    bool ok64 = true;
    #pragma unroll
    for (int i = 0; i < B; i++) {
        long long x = l[i];
        if (x < 1 || x > LK) ok64 = false;
    }
    if (blockIdx.x == 0 && blockIdx.y == 0 && threadIdx.x == 0) {
        #pragma unroll
        for (int i = 0; i < B; i++) g_vlen[i] = ok64 ? (int)l[i] : w[i];
    }

    int mg = blockIdx.x * 32;
    int n0 = blockIdx.y * 64;
    bool is_q = (mg < B * LQ);

    const float *X, *W;
    float* Y;
    int m0;
    if (is_q) { X = query; W = Wq; Y = g_qp; m0 = mg; }
    else {
        m0 = mg - B * LQ;
        int bb = m0 >> 10;
        int krow = m0 & 1023;
        int vb = ok64 ? (int)l[bb] : w[bb];
        if (krow >= vb) return;          // tile fully masked downstream
        X = key; W = Wk; Y = g_kp;
    }

    // Fragment smem: Af[buf][c*2+f][lane] (c=k8 chunk 0..3, f=m16 0..1)
    //                Bf[buf][c*8+s8][lane] (s8 = n8 subtile 0..7)
    __shared__ uint4 Af[2][8][32];
    __shared__ uint2 Bf[2][32][32];

    int tid  = threadIdx.x;
    int lane = tid & 31;
    int wf   = tid >> 5;                 // warp 0..7
    int g  = lane >> 2;                  // 0..7
    int t4 = lane & 3;                   // 0..3

    float ar[4], br[4][2];

    // LDG tile kt into regs (A: 1 frag/thread; B: 4 frag-lanes/thread)
    auto ldg_tile = [&](int kt) {
        {
            int c = wf >> 1, f = wf & 1;
            const float* p = X + (size_t)(m0 + f * 16 + g) * D + kt * 32 + c * 8 + t4;
            ar[0] = p[0];
            ar[1] = p[8 * D];
            ar[2] = p[4];
            ar[3] = p[8 * D + 4];
        }
        #pragma unroll
        for (int j = 0; j < 4; j++) {
            int fragIdx = wf + 8 * j;        // 0..31
            int c = fragIdx >> 3, s8 = fragIdx & 7;
            const float* p = W + (size_t)(n0 + s8 * 8 + g) * D + kt * 32 + c * 8 + t4;
            br[j][0] = p[0];
            br[j][1] = p[4];
        }
    };
    auto sts_tile = [&](int buf) {
        Af[buf][wf][lane] = make_uint4(
            to_tf32(ar[0]), to_tf32(ar[1]), to_tf32(ar[2]), to_tf32(ar[3]));
        #pragma unroll
        for (int j = 0; j < 4; j++) {
            int fragIdx = wf + 8 * j;
            Bf[buf][fragIdx][lane] = make_uint2(to_tf32(br[j][0]), to_tf32(br[j][1]));
        }
    };

    ldg_tile(0);
    sts_tile(0);
    __syncthreads();

    float acc[2][4] = {};                // [f][4] ; warp owns n8 = wf

    const int NT = D / 32;               // 16 tiles
    for (int t = 0; t < NT; t++) {
        int buf = t & 1;
        if (t + 1 < NT) ldg_tile(t + 1);

        #pragma unroll
        for (int c = 0; c < 4; c++) {
            uint4 a0 = Af[buf][c * 2 + 0][lane];
            uint4 a1 = Af[buf][c * 2 + 1][lane];
            uint2 bf = Bf[buf][c * 8 + wf][lane];
            mma_tf32(acc[0][0], acc[0][1], acc[0][2], acc[0][3],
                     a0.x, a0.y, a0.z, a0.w, bf.x, bf.y);
            mma_tf32(acc[1][0], acc[1][1], acc[1][2], acc[1][3],
                     a1.x, a1.y, a1.z, a1.w, bf.x, bf.y);
        }

        if (t + 1 < NT) sts_tile(buf ^ 1);
        __syncthreads();
    }

    // epilogue: c0=(g,2t4) c1=(g,2t4+1) c2=(g+8,2t4) c3=(g+8,2t4+1)
    #pragma unroll
    for (int f = 0; f < 2; f++) {
        int row = m0 + f * 16 + g;
        int col = n0 + wf * 8 + 2 * t4;
        *(float2*)(Y + (size_t)row * UNITS + col) =
            make_float2(acc[f][0], acc[f][1]);
        *(float2*)(Y + (size_t)(row + 8) * UNITS + col) =
            make_float2(acc[f][2], acc[f][3]);
    }
}

// ---------------------------------------------------------------------------
// 2) Scores: warp per k, 8 q-rows, prefetch + butterfly reduce.
//    k-tile = 32 -> grid (32,16,4) = 2048 CTAs for wave balance.
// ---------------------------------------------------------------------------
__global__ __launch_bounds__(256) void score_kernel(const float* __restrict__ vvec)
{
    int b    = blockIdx.z;
    int q0   = blockIdx.y * 8;
    int k0   = blockIdx.x * 32;
    int vlen = g_vlen[b];
    if (k0 >= vlen) return;
    int kmax = min(k0 + 32, vlen);

    int lane = threadIdx.x & 31;
    int wid  = threadIdx.x >> 5;

    int k = k0 + wid;
    if (k >= kmax) return;

    float vr[8];
    {
        float4 a = *(const float4*)(vvec + lane * 8);
        float4 c = *(const float4*)(vvec + lane * 8 + 4);
        vr[0] = a.x; vr[1] = a.y; vr[2] = a.z; vr[3] = a.w;
        vr[4] = c.x; vr[5] = c.y; vr[6] = c.z; vr[7] = c.w;
    }
    float qv[8][8];
    #pragma unroll
    for (int qq = 0; qq < 8; qq++) {
        const float* qr = g_qp + (size_t)(b * LQ + q0 + qq) * UNITS + lane * 8;
        float4 a = *(const float4*)qr;
        float4 c = *(const float4*)(qr + 4);
        qv[qq][0] = a.x; qv[qq][1] = a.y; qv[qq][2] = a.z; qv[qq][3] = a.w;
        qv[qq][4] = c.x; qv[qq][5] = c.y; qv[qq][6] = c.z; qv[qq][7] = c.w;
    }

    const float* kpb = g_kp + (size_t)b * LK * UNITS;
    float*       scb = g_sc + (size_t)(b * LQ + q0) * LK;

    int qq_out = 4 * ((lane >> 2) & 1) + 2 * ((lane >> 3) & 1) + ((lane >> 4) & 1);
    bool writer = (lane & 3) == 0;
    float* wptr = scb + (size_t)qq_out * LK;

    float4 ka, kb;
    {
        const float* kr = kpb + (size_t)k * UNITS + lane * 8;
        ka = *(const float4*)kr;
        kb = *(const float4*)(kr + 4);
    }

    while (k < kmax) {
        int kn = k + 8;
        float4 kan, kbn;
        if (kn < kmax) {
            const float* krn = kpb + (size_t)kn * UNITS + lane * 8;
            kan = *(const float4*)krn;
            kbn = *(const float4*)(krn + 4);
        }

        float kv[8] = {ka.x, ka.y, ka.z, ka.w, kb.x, kb.y, kb.z, kb.w};
        float s[8] = {0.f, 0.f, 0.f, 0.f, 0.f, 0.f, 0.f, 0.f};
        #pragma unroll
        for (int j = 0; j < 8; j++) {
            float kj = kv[j];
            float vj = vr[j];
            #pragma unroll
            for (int qq = 0; qq < 8; qq++)
                s[qq] = fmaf(vj, tanh_fast(qv[qq][j] + kj), s[qq]);
        }

        #define FOLD(dst, a0_, b0_, m)                                   \
            {                                                            \
                float x_ = (lane & (m)) ? (b0_) : (a0_);                 \
                float y_ = (lane & (m)) ? (a0_) : (b0_);                 \
                dst = x_ + __shfl_xor_sync(0xFFFFFFFFu, y_, (m));        \
            }
        float t0, t1, t2, t3, u0, u1, v;
        FOLD(t0, s[0], s[1], 16)
        FOLD(t1, s[2], s[3], 16)
        FOLD(t2, s[4], s[5], 16)
        FOLD(t3, s[6], s[7], 16)
        FOLD(u0, t0, t1, 8)
        FOLD(u1, t2, t3, 8)
        FOLD(v,  u0, u1, 4)
        v += __shfl_xor_sync(0xFFFFFFFFu, v, 2);
        v += __shfl_xor_sync(0xFFFFFFFFu, v, 1);
        #undef FOLD

        if (writer) wptr[k] = v;

        ka = kan; kb = kbn;
        k = kn;
    }
}

// ---------------------------------------------------------------------------
// 3) Fused softmax + output GEMM (unchanged).
// ---------------------------------------------------------------------------
__global__ __launch_bounds__(256) void out_kernel(
    const float* __restrict__ value, float* __restrict__ out)
{
    __shared__ float As[32][34];
    __shared__ float Bs[32][64];
    __shared__ float rmax[32], rinv[32];

    int b    = blockIdx.z;
    int m0   = blockIdx.x * 32;
    int n0   = blockIdx.y * 64;
    int vlen = g_vlen[b];
    int kend = (vlen + 31) & ~31;

    const float* S = g_sc  + (size_t)(b * LQ + m0) * LK;
    const float* V = value + (size_t)b * LK * DV;

    int tid  = threadIdx.x;
    int lane = tid & 31;
    int wid  = tid >> 5;

    for (int r = wid; r < 32; r += 8) {
        const float* srow = S + (size_t)r * LK;
        float m = -3.0e38f;
        for (int k = lane; k < vlen; k += 32) m = fmaxf(m, srow[k]);
        #pragma unroll
        for (int off = 16; off > 0; off >>= 1)
            m = fmaxf(m, __shfl_xor_sync(0xFFFFFFFFu, m, off));
        float s = 0.f;
        for (int k = lane; k < vlen; k += 32) s += __expf(srow[k] - m);
        #pragma unroll
        for (int off = 16; off > 0; off >>= 1)
            s += __shfl_xor_sync(0xFFFFFFFFu, s, off);
        if (lane == 0) { rmax[r] = m; rinv[r] = 1.0f / s; }
    }
    __syncthreads();

    int ty = tid >> 4, tx = tid & 15;
    int am = tid >> 3, ak = (tid & 7) * 4;
    int bk = tid >> 3, bn = (tid & 7) * 8;

    ull acc[2][2] = {};

    for (int k0 = 0; k0 < kend; k0 += 32) {
        float4 sv = *(const float4*)(S + (size_t)am * LK + k0 + ak);
        float mr = rmax[am];
        int kg = k0 + ak;
        As[ak + 0][am] = (kg + 0 < vlen) ? __expf(sv.x - mr) : 0.f;
        As[ak + 1][am] = (kg + 1 < vlen) ? __expf(sv.y - mr) : 0.f;
        As[ak + 2][am] = (kg + 2 < vlen) ? __expf(sv.z - mr) : 0.f;
        As[ak + 3][am] = (kg + 3 < vlen) ? __expf(sv.w - mr) : 0.f;

        const float* vp = V + (size_t)(k0 + bk) * DV + n0 + bn;
        *(float4*)&Bs[bk][bn]     = *(const float4*)(vp);
        *(float4*)&Bs[bk][bn + 4] = *(const float4*)(vp + 4);
        __syncthreads();

        #pragma unroll
        for (int kk = 0; kk < 32; kk++) {
            float2 af = *(const float2*)&As[kk][ty * 2];
            ull ap0 = dup2(af.x);
            ull ap1 = dup2(af.y);
            longlong2 bv = *(const longlong2*)&Bs[kk][tx * 4];
            acc[0][0] = ffma2(ap0, (ull)bv.x, acc[0][0]);
            acc[0][1] = ffma2(ap0, (ull)bv.y, acc[0][1]);
            acc[1][0] = ffma2(ap1, (ull)bv.x, acc[1][0]);
            acc[1][1] = ffma2(ap1, (ull)bv.y, acc[1][1]);
        }
        __syncthreads();
    }

    #pragma unroll
    for (int i = 0; i < 2; i++) {
        int r = ty * 2 + i;
        float inv = rinv[r];
        float2 r0 = unpack2(acc[i][0]);
        float2 r1 = unpack2(acc[i][1]);
        *(float4*)(out + (size_t)(b * LQ + m0 + r) * DV + n0 + tx * 4) =
            make_float4(r0.x * inv, r0.y * inv, r1.x * inv, r1.y * inv);
    }
}

// ---------------------------------------------------------------------------
// kernel_launch — inputs: query, key, value, valid_len, W_q, W_k, v
// ---------------------------------------------------------------------------
extern "C" void kernel_launch(void* const* d_in, const int* in_sizes, int n_in,
                              void* d_out, int out_size)
{
    const float* query = (const float*)d_in[0];
    const float* key   = (const float*)d_in[1];
    const float* value = (const float*)d_in[2];
    const void*  vlen  = d_in[3];
    const float* W_q   = (const float*)d_in[4];
    const float* W_k   = (const float*)d_in[5];
    const float* vvec  = (const float*)d_in[6];
    float* out = (float*)d_out;

    // 1) fused q+k projection via tf32 mma: 144 x 4 = 576 CTAs, 256 thr
    proj_kernel<<<dim3((B * LQ + B * LK) / 32, UNITS / 64), 256>>>(
        query, key, W_q, W_k, vlen);

    // 2) scores: 32 x 16 x 4 = 2048 CTAs, 256 thr (masked tiles exit)
    score_kernel<<<dim3(LK / 32, LQ / 8, B), 256>>>(vvec);

    // 3) fused softmax + output GEMM: 4 x 8 x 4 = 128 CTAs
    out_kernel<<<dim3(LQ / 32, DV / 64, B), 256>>>(value, out);
}

// round 11
// speedup vs baseline: 1.1709x; 1.1709x over previous
#include <cuda_runtime.h>
#include <cuda_bf16.h>
#include <stdint.h>

#define B     4
#define LQ    128
#define LK    1024
#define D     512
#define DV    512
#define UNITS 256

typedef unsigned long long ull;

// Scratch (device globals — no allocation allowed)
__device__ float g_qp[B * LQ * UNITS];         // [b*LQ+q][u]
__device__ float g_kp[B * LK * UNITS];         // [b*LK+k][u]
__device__ float g_sc[B * LQ * LK];            // raw scores (unmasked region)
__device__ int   g_vlen[B];

__device__ __forceinline__ float tanh_fast(float x) {
    float y;
    asm("tanh.approx.f32 %0, %1;" : "=f"(y) : "f"(x));
    return y;
}
__device__ __forceinline__ ull ffma2(ull a, ull b, ull c) {
    ull d;
    asm("fma.rn.f32x2 %0, %1, %2, %3;" : "=l"(d) : "l"(a), "l"(b), "l"(c));
    return d;
}
__device__ __forceinline__ ull dup2(float x) {
    ull r;
    asm("mov.b64 %0, {%1, %1};" : "=l"(r) : "f"(x));
    return r;
}
__device__ __forceinline__ float2 unpack2(ull v) {
    float2 f;
    asm("mov.b64 {%0, %1}, %2;" : "=f"(f.x), "=f"(f.y) : "l"(v));
    return f;
}
__device__ __forceinline__ uint32_t to_tf32(float x) {
    uint32_t r;
    asm("cvt.rna.tf32.f32 %0, %1;" : "=r"(r) : "f"(x));
    return r;
}
__device__ __forceinline__ void mma_tf32(
    float& d0, float& d1, float& d2, float& d3,
    uint32_t a0, uint32_t a1, uint32_t a2, uint32_t a3,
    uint32_t b0, uint32_t b1)
{
    asm("mma.sync.aligned.m16n8k8.row.col.f32.tf32.tf32.f32 "
        "{%0,%1,%2,%3}, {%4,%5,%6,%7}, {%8,%9}, {%0,%1,%2,%3};"
        : "+f"(d0), "+f"(d1), "+f"(d2), "+f"(d3)
        : "r"(a0), "r"(a1), "r"(a2), "r"(a3), "r"(b0), "r"(b1));
}

// ---------------------------------------------------------------------------
// 1) Projection GEMM via tf32 mma.sync (EXACT R9 config — best measured).
//    CTA 64m x 64n, BK=32, 256 thr = 8 warps (2m x 4n), warp tile 32x16.
//    Fragment-native smem; grid 72 x 4 = 288 CTAs; masked k-tiles exit.
// ---------------------------------------------------------------------------
__global__ __launch_bounds__(256) void proj_kernel(
    const float* __restrict__ query, const float* __restrict__ key,
    const float* __restrict__ Wq,    const float* __restrict__ Wk,
    const void*  __restrict__ vl)
{
    const long long* l = (const long long*)vl;
    const int*       w = (const int*)vl;
    bool ok64 = true;
    #pragma unroll
    for (int i = 0; i < B; i++) {
        long long x = l[i];
        if (x < 1 || x > LK) ok64 = false;
    }
    if (blockIdx.x == 0 && blockIdx.y == 0 && threadIdx.x == 0) {
        #pragma unroll
        for (int i = 0; i < B; i++) g_vlen[i] = ok64 ? (int)l[i] : w[i];
    }

    int mg = blockIdx.x * 64;
    int n0 = blockIdx.y * 64;
    bool is_q = (mg < B * LQ);

    const float *X, *W;
    float* Y;
    int m0;
    if (is_q) { X = query; W = Wq; Y = g_qp; m0 = mg; }
    else {
        m0 = mg - B * LQ;
        int bb = m0 >> 10;
        int krow = m0 & 1023;
        int vb = ok64 ? (int)l[bb] : w[bb];
        if (krow >= vb) return;          // tile fully masked downstream
        X = key; W = Wk; Y = g_kp;
    }

    __shared__ uint4 Af[2][16][32];
    __shared__ uint2 Bf[2][32][32];

    int tid  = threadIdx.x;
    int lane = tid & 31;
    int wf   = tid >> 5;
    int warpM = wf >> 2;                 // 0..1
    int warpN = wf & 3;                  // 0..3
    int g  = lane >> 2;                  // 0..7
    int t4 = lane & 3;                   // 0..3

    float ar[2][4], br[4][2];

    auto ldg_tile = [&](int kt) {
        #pragma unroll
        for (int j = 0; j < 2; j++) {
            int fragIdx = wf + 8 * j;        // 0..15
            int c = fragIdx >> 2, f = fragIdx & 3;
            const float* p = X + (size_t)(m0 + f * 16 + g) * D + kt * 32 + c * 8 + t4;
            ar[j][0] = p[0];
            ar[j][1] = p[8 * D];
            ar[j][2] = p[4];
            ar[j][3] = p[8 * D + 4];
        }
        #pragma unroll
        for (int j = 0; j < 4; j++) {
            int fragIdx = wf + 8 * j;        // 0..31
            int c = fragIdx >> 3, s8 = fragIdx & 7;
            const float* p = W + (size_t)(n0 + s8 * 8 + g) * D + kt * 32 + c * 8 + t4;
            br[j][0] = p[0];
            br[j][1] = p[4];
        }
    };
    auto sts_tile = [&](int buf) {
        #pragma unroll
        for (int j = 0; j < 2; j++) {
            int fragIdx = wf + 8 * j;
            Af[buf][fragIdx][lane] = make_uint4(
                to_tf32(ar[j][0]), to_tf32(ar[j][1]),
                to_tf32(ar[j][2]), to_tf32(ar[j][3]));
        }
        #pragma unroll
        for (int j = 0; j < 4; j++) {
            int fragIdx = wf + 8 * j;
            Bf[buf][fragIdx][lane] = make_uint2(to_tf32(br[j][0]), to_tf32(br[j][1]));
        }
    };

    ldg_tile(0);
    sts_tile(0);
    __syncthreads();

    float acc[2][2][4] = {};             // [fi][ni][4]

    const int NT = D / 32;               // 16 tiles
    for (int t = 0; t < NT; t++) {
        int buf = t & 1;
        if (t + 1 < NT) ldg_tile(t + 1);

        #pragma unroll
        for (int c = 0; c < 4; c++) {
            uint4 afr[2];
            uint2 bfr[2];
            #pragma unroll
            for (int fi = 0; fi < 2; fi++)
                afr[fi] = Af[buf][c * 4 + warpM * 2 + fi][lane];
            #pragma unroll
            for (int ni = 0; ni < 2; ni++)
                bfr[ni] = Bf[buf][c * 8 + warpN * 2 + ni][lane];
            #pragma unroll
            for (int fi = 0; fi < 2; fi++)
                #pragma unroll
                for (int ni = 0; ni < 2; ni++)
                    mma_tf32(acc[fi][ni][0], acc[fi][ni][1],
                             acc[fi][ni][2], acc[fi][ni][3],
                             afr[fi].x, afr[fi].y, afr[fi].z, afr[fi].w,
                             bfr[ni].x, bfr[ni].y);
        }

        if (t + 1 < NT) sts_tile(buf ^ 1);
        __syncthreads();
    }

    #pragma unroll
    for (int fi = 0; fi < 2; fi++) {
        #pragma unroll
        for (int ni = 0; ni < 2; ni++) {
            int row = m0 + warpM * 32 + fi * 16 + g;
            int col = n0 + warpN * 16 + ni * 8 + 2 * t4;
            *(float2*)(Y + (size_t)row * UNITS + col) =
                make_float2(acc[fi][ni][0], acc[fi][ni][1]);
            *(float2*)(Y + (size_t)(row + 8) * UNITS + col) =
                make_float2(acc[fi][ni][2], acc[fi][ni][3]);
        }
    }
}

// ---------------------------------------------------------------------------
// 2) Scores (EXACT R10 config — best measured): warp per k, 8 q-rows,
//    prefetch + butterfly reduce, k-tile 32, grid (32,16,4) = 2048 CTAs.
// ---------------------------------------------------------------------------
__global__ __launch_bounds__(256) void score_kernel(const float* __restrict__ vvec)
{
    int b    = blockIdx.z;
    int q0   = blockIdx.y * 8;
    int k0   = blockIdx.x * 32;
    int vlen = g_vlen[b];
    if (k0 >= vlen) return;
    int kmax = min(k0 + 32, vlen);

    int lane = threadIdx.x & 31;
    int wid  = threadIdx.x >> 5;

    int k = k0 + wid;
    if (k >= kmax) return;

    float vr[8];
    {
        float4 a = *(const float4*)(vvec + lane * 8);
        float4 c = *(const float4*)(vvec + lane * 8 + 4);
        vr[0] = a.x; vr[1] = a.y; vr[2] = a.z; vr[3] = a.w;
        vr[4] = c.x; vr[5] = c.y; vr[6] = c.z; vr[7] = c.w;
    }
    float qv[8][8];
    #pragma unroll
    for (int qq = 0; qq < 8; qq++) {
        const float* qr = g_qp + (size_t)(b * LQ + q0 + qq) * UNITS + lane * 8;
        float4 a = *(const float4*)qr;
        float4 c = *(const float4*)(qr + 4);
        qv[qq][0] = a.x; qv[qq][1] = a.y; qv[qq][2] = a.z; qv[qq][3] = a.w;
        qv[qq][4] = c.x; qv[qq][5] = c.y; qv[qq][6] = c.z; qv[qq][7] = c.w;
    }

    const float* kpb = g_kp + (size_t)b * LK * UNITS;
    float*       scb = g_sc + (size_t)(b * LQ + q0) * LK;

    int qq_out = 4 * ((lane >> 2) & 1) + 2 * ((lane >> 3) & 1) + ((lane >> 4) & 1);
    bool writer = (lane & 3) == 0;
    float* wptr = scb + (size_t)qq_out * LK;

    float4 ka, kb;
    {
        const float* kr = kpb + (size_t)k * UNITS + lane * 8;
        ka = *(const float4*)kr;
        kb = *(const float4*)(kr + 4);
    }

    while (k < kmax) {
        int kn = k + 8;
        float4 kan, kbn;
        if (kn < kmax) {
            const float* krn = kpb + (size_t)kn * UNITS + lane * 8;
            kan = *(const float4*)krn;
            kbn = *(const float4*)(krn + 4);
        }

        float kv[8] = {ka.x, ka.y, ka.z, ka.w, kb.x, kb.y, kb.z, kb.w};
        float s[8] = {0.f, 0.f, 0.f, 0.f, 0.f, 0.f, 0.f, 0.f};
        #pragma unroll
        for (int j = 0; j < 8; j++) {
            float kj = kv[j];
            float vj = vr[j];
            #pragma unroll
            for (int qq = 0; qq < 8; qq++)
                s[qq] = fmaf(vj, tanh_fast(qv[qq][j] + kj), s[qq]);
        }

        #define FOLD(dst, a0_, b0_, m)                                   \
            {                                                            \
                float x_ = (lane & (m)) ? (b0_) : (a0_);                 \
                float y_ = (lane & (m)) ? (a0_) : (b0_);                 \
                dst = x_ + __shfl_xor_sync(0xFFFFFFFFu, y_, (m));        \
            }
        float t0, t1, t2, t3, u0, u1, v;
        FOLD(t0, s[0], s[1], 16)
        FOLD(t1, s[2], s[3], 16)
        FOLD(t2, s[4], s[5], 16)
        FOLD(t3, s[6], s[7], 16)
        FOLD(u0, t0, t1, 8)
        FOLD(u1, t2, t3, 8)
        FOLD(v,  u0, u1, 4)
        v += __shfl_xor_sync(0xFFFFFFFFu, v, 2);
        v += __shfl_xor_sync(0xFFFFFFFFu, v, 1);
        #undef FOLD

        if (writer) wptr[k] = v;

        ka = kan; kb = kbn;
        k = kn;
    }
}

// ---------------------------------------------------------------------------
// 3) Fused softmax + output GEMM (unchanged).
// ---------------------------------------------------------------------------
__global__ __launch_bounds__(256) void out_kernel(
    const float* __restrict__ value, float* __restrict__ out)
{
    __shared__ float As[32][34];
    __shared__ float Bs[32][64];
    __shared__ float rmax[32], rinv[32];

    int b    = blockIdx.z;
    int m0   = blockIdx.x * 32;
    int n0   = blockIdx.y * 64;
    int vlen = g_vlen[b];
    int kend = (vlen + 31) & ~31;

    const float* S = g_sc  + (size_t)(b * LQ + m0) * LK;
    const float* V = value + (size_t)b * LK * DV;

    int tid  = threadIdx.x;
    int lane = tid & 31;
    int wid  = tid >> 5;

    for (int r = wid; r < 32; r += 8) {
        const float* srow = S + (size_t)r * LK;
        float m = -3.0e38f;
        for (int k = lane; k < vlen; k += 32) m = fmaxf(m, srow[k]);
        #pragma unroll
        for (int off = 16; off > 0; off >>= 1)
            m = fmaxf(m, __shfl_xor_sync(0xFFFFFFFFu, m, off));
        float s = 0.f;
        for (int k = lane; k < vlen; k += 32) s += __expf(srow[k] - m);
        #pragma unroll
        for (int off = 16; off > 0; off >>= 1)
            s += __shfl_xor_sync(0xFFFFFFFFu, s, off);
        if (lane == 0) { rmax[r] = m; rinv[r] = 1.0f / s; }
    }
    __syncthreads();

    int ty = tid >> 4, tx = tid & 15;
    int am = tid >> 3, ak = (tid & 7) * 4;
    int bk = tid >> 3, bn = (tid & 7) * 8;

    ull acc[2][2] = {};

    for (int k0 = 0; k0 < kend; k0 += 32) {
        float4 sv = *(const float4*)(S + (size_t)am * LK + k0 + ak);
        float mr = rmax[am];
        int kg = k0 + ak;
        As[ak + 0][am] = (kg + 0 < vlen) ? __expf(sv.x - mr) : 0.f;
        As[ak + 1][am] = (kg + 1 < vlen) ? __expf(sv.y - mr) : 0.f;
        As[ak + 2][am] = (kg + 2 < vlen) ? __expf(sv.z - mr) : 0.f;
        As[ak + 3][am] = (kg + 3 < vlen) ? __expf(sv.w - mr) : 0.f;

        const float* vp = V + (size_t)(k0 + bk) * DV + n0 + bn;
        *(float4*)&Bs[bk][bn]     = *(const float4*)(vp);
        *(float4*)&Bs[bk][bn + 4] = *(const float4*)(vp + 4);
        __syncthreads();

        #pragma unroll
        for (int kk = 0; kk < 32; kk++) {
            float2 af = *(const float2*)&As[kk][ty * 2];
            ull ap0 = dup2(af.x);
            ull ap1 = dup2(af.y);
            longlong2 bv = *(const longlong2*)&Bs[kk][tx * 4];
            acc[0][0] = ffma2(ap0, (ull)bv.x, acc[0][0]);
            acc[0][1] = ffma2(ap0, (ull)bv.y, acc[0][1]);
            acc[1][0] = ffma2(ap1, (ull)bv.x, acc[1][0]);
            acc[1][1] = ffma2(ap1, (ull)bv.y, acc[1][1]);
        }
        __syncthreads();
    }

    #pragma unroll
    for (int i = 0; i < 2; i++) {
        int r = ty * 2 + i;
        float inv = rinv[r];
        float2 r0 = unpack2(acc[i][0]);
        float2 r1 = unpack2(acc[i][1]);
        *(float4*)(out + (size_t)(b * LQ + m0 + r) * DV + n0 + tx * 4) =
            make_float4(r0.x * inv, r0.y * inv, r1.x * inv, r1.y * inv);
    }
}

// ---------------------------------------------------------------------------
// kernel_launch — inputs: query, key, value, valid_len, W_q, W_k, v
// ---------------------------------------------------------------------------
extern "C" void kernel_launch(void* const* d_in, const int* in_sizes, int n_in,
                              void* d_out, int out_size)
{
    const float* query = (const float*)d_in[0];
    const float* key   = (const float*)d_in[1];
    const float* value = (const float*)d_in[2];
    const void*  vlen  = d_in[3];
    const float* W_q   = (const float*)d_in[4];
    const float* W_k   = (const float*)d_in[5];
    const float* vvec  = (const float*)d_in[6];
    float* out = (float*)d_out;

    // 1) fused q+k projection via tf32 mma: 72 x 4 = 288 CTAs, 256 thr
    proj_kernel<<<dim3((B * LQ + B * LK) / 64, UNITS / 64), 256>>>(
        query, key, W_q, W_k, vlen);

    // 2) scores: 32 x 16 x 4 = 2048 CTAs, 256 thr (masked tiles exit)
    score_kernel<<<dim3(LK / 32, LQ / 8, B), 256>>>(vvec);

    // 3) fused softmax + output GEMM: 4 x 8 x 4 = 128 CTAs
    out_kernel<<<dim3(LQ / 32, DV / 64, B), 256>>>(value, out);
}